// round 1
// baseline (speedup 1.0000x reference)
#include <cuda_runtime.h>
#include <math.h>

#define BB 2
#define TT 2048
#define CC 1024
#define HH 16
#define DHH 64
#define NROWS (BB*TT)   // 4096

// ---------------- scratch (static device allocations; no cudaMalloc) -------
__device__ float g_qw[CC*CC];
__device__ float g_kw[CC*CC];
__device__ float g_vw[CC*CC];
__device__ float g_q[NROWS*CC];
__device__ float g_k[NROWS*CC];
__device__ float g_v[NROWS*CC];
__device__ float g_y[NROWS*CC];
__device__ float g_ga[NROWS*HH];

// ---------------- 1) fuse mix into weights ---------------------------------
// out[h*64+d][c] = sum_m mix[h][m] * W[m*64+d][c]
__global__ void fuse_kernel(const float* __restrict__ cq, const float* __restrict__ ck,
                            const float* __restrict__ cv, const float* __restrict__ qm,
                            const float* __restrict__ km, const float* __restrict__ vm) {
    int row = blockIdx.x;
    int wi  = blockIdx.y;
    const float* W = (wi == 0) ? cq : (wi == 1) ? ck : cv;
    const float* M = (wi == 0) ? qm : (wi == 1) ? km : vm;
    float* O       = (wi == 0) ? g_qw : (wi == 1) ? g_kw : g_vw;
    int h = row >> 6, d = row & 63;
    float mx[16];
#pragma unroll
    for (int m = 0; m < 16; m++) mx[m] = M[h*16 + m];
    for (int c = threadIdx.x; c < CC; c += blockDim.x) {
        float s = 0.f;
#pragma unroll
        for (int m = 0; m < 16; m++) s += mx[m] * W[(m*64 + d)*CC + c];
        O[row*CC + c] = s;
    }
}

// ---------------- 2) NT SGEMM: C[i][j] = sum_k A[i][k]*B[j][k] --------------
// 128x128 tile, BK=8, 256 threads, 8x8 micro-tile per thread.
__global__ __launch_bounds__(256) void gemm_nt_kernel(
    const float* __restrict__ A, const float* __restrict__ Bm,
    float* __restrict__ Cm, int M, int N, int K) {
    __shared__ float As[8][132];
    __shared__ float Bs[8][132];
    const int tid = threadIdx.x;
    const int tx = tid & 15, ty = tid >> 4;
    const int brow = blockIdx.x * 128, bcol = blockIdx.y * 128;

    const int lr = tid >> 1;          // 0..127
    const int lc = (tid & 1) * 4;     // 0 or 4
    const float* Abase = A  + (size_t)(brow + lr) * K + lc;
    const float* Bbase = Bm + (size_t)(bcol + lr) * K + lc;

    float acc[8][8];
#pragma unroll
    for (int i = 0; i < 8; i++)
#pragma unroll
        for (int j = 0; j < 8; j++) acc[i][j] = 0.f;

    float4 acur = *(const float4*)Abase;
    float4 bcur = *(const float4*)Bbase;

    for (int kk = 0; kk < K; kk += 8) {
        As[lc+0][lr] = acur.x; As[lc+1][lr] = acur.y;
        As[lc+2][lr] = acur.z; As[lc+3][lr] = acur.w;
        Bs[lc+0][lr] = bcur.x; Bs[lc+1][lr] = bcur.y;
        Bs[lc+2][lr] = bcur.z; Bs[lc+3][lr] = bcur.w;
        __syncthreads();
        if (kk + 8 < K) {
            acur = *(const float4*)(Abase + kk + 8);
            bcur = *(const float4*)(Bbase + kk + 8);
        }
#pragma unroll
        for (int k = 0; k < 8; k++) {
            float4 a0 = *(const float4*)&As[k][ty*8];
            float4 a1 = *(const float4*)&As[k][ty*8 + 4];
            float4 b0 = *(const float4*)&Bs[k][tx*8];
            float4 b1 = *(const float4*)&Bs[k][tx*8 + 4];
            float ar[8] = {a0.x,a0.y,a0.z,a0.w,a1.x,a1.y,a1.z,a1.w};
            float br[8] = {b0.x,b0.y,b0.z,b0.w,b1.x,b1.y,b1.z,b1.w};
#pragma unroll
            for (int i = 0; i < 8; i++)
#pragma unroll
                for (int j = 0; j < 8; j++) acc[i][j] += ar[i]*br[j];
        }
        __syncthreads();
    }
#pragma unroll
    for (int i = 0; i < 8; i++) {
        int row = brow + ty*8 + i;
        float* dst = Cm + (size_t)row * N + bcol + tx*8;
        float4 w0 = {acc[i][0], acc[i][1], acc[i][2], acc[i][3]};
        float4 w1 = {acc[i][4], acc[i][5], acc[i][6], acc[i][7]};
        *(float4*)dst = w0;
        *(float4*)(dst + 4) = w1;
    }
}

// ---------------- 3) gates + RoPE + RMSNorm (one warp per (b,t,h)) ----------
__global__ void post_kernel(const float* __restrict__ x, const float* __restrict__ ve,
                            const float* __restrict__ cosb, const float* __restrict__ sinb,
                            const float* __restrict__ vgw, const float* __restrict__ agw) {
    int gw   = (blockIdx.x * blockDim.x + threadIdx.x) >> 5;
    int lane = threadIdx.x & 31;
    if (gw >= NROWS*HH) return;
    int h  = gw % HH;
    int bt = gw / HH;           // b*T + t
    int t  = bt % TT;
    size_t xbase = (size_t)bt * CC;

    // ve gate: 2*sigmoid(x[:32] . vgw[h])
    float gv = x[xbase + lane] * vgw[h*32 + lane];
#pragma unroll
    for (int o = 16; o > 0; o >>= 1) gv += __shfl_xor_sync(0xffffffffu, gv, o);
    float gate_v = 2.f / (1.f + __expf(-gv));

    // attn gate: sigmoid(x[:12] . agw[h])
    float ga = (lane < 12) ? x[xbase + lane] * agw[h*12 + lane] : 0.f;
#pragma unroll
    for (int o = 16; o > 0; o >>= 1) ga += __shfl_xor_sync(0xffffffffu, ga, o);
    if (lane == 0) g_ga[(size_t)bt*HH + h] = 1.f / (1.f + __expf(-ga));

    size_t idx = xbase + h*64;
    // v += gate_v * ve
    g_v[idx + lane]      += gate_v * ve[idx + lane];
    g_v[idx + lane + 32] += gate_v * ve[idx + lane + 32];

    float cs = cosb[t*32 + lane], sn = sinb[t*32 + lane];
    // q: rope then rmsnorm
    {
        float q1 = g_q[idx + lane], q2 = g_q[idx + lane + 32];
        float r1 =  q1*cs + q2*sn;
        float r2 = -q1*sn + q2*cs;
        float ss = r1*r1 + r2*r2;
#pragma unroll
        for (int o = 16; o > 0; o >>= 1) ss += __shfl_xor_sync(0xffffffffu, ss, o);
        float sc = rsqrtf(ss * (1.f/64.f) + 1e-6f);
        g_q[idx + lane] = r1*sc; g_q[idx + lane + 32] = r2*sc;
    }
    // k: rope then rmsnorm (shift handled at attention load time)
    {
        float k1 = g_k[idx + lane], k2 = g_k[idx + lane + 32];
        float r1 =  k1*cs + k2*sn;
        float r2 = -k1*sn + k2*cs;
        float ss = r1*r1 + r2*r2;
#pragma unroll
        for (int o = 16; o > 0; o >>= 1) ss += __shfl_xor_sync(0xffffffffu, ss, o);
        float sc = rsqrtf(ss * (1.f/64.f) + 1e-6f);
        g_k[idx + lane] = r1*sc; g_k[idx + lane + 32] = r2*sc;
    }
}

// ---------------- 4) flash attention, fp32, BM=BN=64, 128 threads ----------
#define SMPAD 68
#define ATTN_SMEM (4*64*SMPAD*4)

__global__ __launch_bounds__(128) void attn_kernel(const int* __restrict__ wsp) {
    extern __shared__ float smf[];
    float* Qs = smf;                 // [d][m] 64x68
    float* Ks = smf + 64*SMPAD;      // [d][n]
    float* Vs = smf + 2*64*SMPAD;    // [n][d]
    float* Ps = smf + 3*64*SMPAD;    // [n][m]

    const int qt = blockIdx.x, h = blockIdx.y, b = blockIdx.z;
    const int tid = threadIdx.x;
    const int tr = tid >> 3;         // 0..15 -> 4 q rows
    const int tc = tid & 7;          // 0..7  -> 8 cols
    const int q0 = qt * 64;

    int wsv = wsp ? *wsp : -1;
    const bool use_w = (wsv >= 0) && (wsv < TT - 1);

    const int m    = tid >> 1;       // 0..63 row loaded by this thread
    const int half = tid & 1;        // 0/1 d-half

    // load Q tile (transposed into [d][m])
    {
        const float* src = g_q + ((size_t)(b*TT + q0 + m))*CC + h*64 + half*32;
#pragma unroll
        for (int i = 0; i < 8; i++) {
            float4 v = *(const float4*)(src + i*4);
            int d = half*32 + i*4;
            Qs[(d+0)*SMPAD + m] = v.x; Qs[(d+1)*SMPAD + m] = v.y;
            Qs[(d+2)*SMPAD + m] = v.z; Qs[(d+3)*SMPAD + m] = v.w;
        }
    }

    float o[4][8];
    float mi[4], li[4];
#pragma unroll
    for (int r = 0; r < 4; r++) {
        mi[r] = -1e30f; li[r] = 0.f;
#pragma unroll
        for (int c = 0; c < 8; c++) o[r][c] = 0.f;
    }

    for (int jt = 0; jt <= qt; jt++) {
        const int kv0 = jt * 64;
        __syncthreads();   // prior PV done with Vs/Ps; Qs visible on first iter
        // load K (with stationary shift on second half) and V
        {
            int pos = kv0 + m;
            int srcpos = (half == 0) ? pos : (pos > 0 ? pos - 1 : 0);
            const float* ks = g_k + ((size_t)(b*TT + srcpos))*CC + h*64 + half*32;
#pragma unroll
            for (int i = 0; i < 8; i++) {
                float4 v = *(const float4*)(ks + i*4);
                int d = half*32 + i*4;
                Ks[(d+0)*SMPAD + m] = v.x; Ks[(d+1)*SMPAD + m] = v.y;
                Ks[(d+2)*SMPAD + m] = v.z; Ks[(d+3)*SMPAD + m] = v.w;
            }
            const float* vs = g_v + ((size_t)(b*TT + pos))*CC + h*64 + half*32;
#pragma unroll
            for (int i = 0; i < 8; i++)
                *(float4*)(Vs + m*SMPAD + half*32 + i*4) = *(const float4*)(vs + i*4);
        }
        __syncthreads();

        // S = Q K^T
        float s[4][8];
#pragma unroll
        for (int r = 0; r < 4; r++)
#pragma unroll
            for (int c = 0; c < 8; c++) s[r][c] = 0.f;
#pragma unroll 16
        for (int d = 0; d < 64; d++) {
            float4 a  = *(const float4*)(Qs + d*SMPAD + tr*4);
            float4 b0 = *(const float4*)(Ks + d*SMPAD + tc*8);
            float4 b1 = *(const float4*)(Ks + d*SMPAD + tc*8 + 4);
            float ar[4] = {a.x, a.y, a.z, a.w};
            float br[8] = {b0.x,b0.y,b0.z,b0.w,b1.x,b1.y,b1.z,b1.w};
#pragma unroll
            for (int r = 0; r < 4; r++)
#pragma unroll
                for (int c = 0; c < 8; c++) s[r][c] += ar[r]*br[c];
        }
        // mask + scale
#pragma unroll
        for (int r = 0; r < 4; r++) {
            int qi = q0 + tr*4 + r;
#pragma unroll
            for (int c = 0; c < 8; c++) {
                int kj = kv0 + tc*8 + c;
                bool ok = (kj <= qi) && (!use_w || (qi - kj) <= wsv);
                s[r][c] = ok ? s[r][c]*0.125f : -1e30f;
            }
        }
        // online softmax (stats replicated over the 8 threads of each row group)
#pragma unroll
        for (int r = 0; r < 4; r++) {
            float mx = s[r][0];
#pragma unroll
            for (int c = 1; c < 8; c++) mx = fmaxf(mx, s[r][c]);
            mx = fmaxf(mx, __shfl_xor_sync(0xffffffffu, mx, 1));
            mx = fmaxf(mx, __shfl_xor_sync(0xffffffffu, mx, 2));
            mx = fmaxf(mx, __shfl_xor_sync(0xffffffffu, mx, 4));
            float mnew = fmaxf(mi[r], mx);
            float corr = __expf(mi[r] - mnew);
            float sum = 0.f;
#pragma unroll
            for (int c = 0; c < 8; c++) {
                float p = __expf(s[r][c] - mnew);
                s[r][c] = p; sum += p;
            }
            sum += __shfl_xor_sync(0xffffffffu, sum, 1);
            sum += __shfl_xor_sync(0xffffffffu, sum, 2);
            sum += __shfl_xor_sync(0xffffffffu, sum, 4);
            li[r] = li[r]*corr + sum;
            mi[r] = mnew;
#pragma unroll
            for (int c = 0; c < 8; c++) o[r][c] *= corr;
            // write P transposed [n][m]
#pragma unroll
            for (int c = 0; c < 8; c++)
                Ps[(tc*8 + c)*SMPAD + tr*4 + r] = s[r][c];
        }
        __syncthreads();

        // O += P V
#pragma unroll 16
        for (int n = 0; n < 64; n++) {
            float4 p  = *(const float4*)(Ps + n*SMPAD + tr*4);
            float4 v0 = *(const float4*)(Vs + n*SMPAD + tc*8);
            float4 v1 = *(const float4*)(Vs + n*SMPAD + tc*8 + 4);
            float pr[4] = {p.x, p.y, p.z, p.w};
            float vr[8] = {v0.x,v0.y,v0.z,v0.w,v1.x,v1.y,v1.z,v1.w};
#pragma unroll
            for (int r = 0; r < 4; r++)
#pragma unroll
                for (int c = 0; c < 8; c++) o[r][c] += pr[r]*vr[c];
        }
    }

    // epilogue: normalize, apply attn gate, write y
#pragma unroll
    for (int r = 0; r < 4; r++) {
        int qi = q0 + tr*4 + r;
        float g = g_ga[(size_t)(b*TT + qi)*HH + h];
        float inv = g / li[r];
        float* dst = g_y + ((size_t)(b*TT + qi))*CC + h*64 + tc*8;
        float4 w0 = {o[r][0]*inv, o[r][1]*inv, o[r][2]*inv, o[r][3]*inv};
        float4 w1 = {o[r][4]*inv, o[r][5]*inv, o[r][6]*inv, o[r][7]*inv};
        *(float4*)dst = w0;
        *(float4*)(dst + 4) = w1;
    }
}

// ---------------- launch ----------------------------------------------------
extern "C" void kernel_launch(void* const* d_in, const int* in_sizes, int n_in,
                              void* d_out, int out_size) {
    const float* x    = (const float*)d_in[0];
    const float* ve   = (const float*)d_in[1];
    const float* cosb = (const float*)d_in[2];
    const float* sinb = (const float*)d_in[3];
    const float* cqw  = (const float*)d_in[4];
    const float* ckw  = (const float*)d_in[5];
    const float* cvw  = (const float*)d_in[6];
    const float* cpw  = (const float*)d_in[7];
    const float* vgw  = (const float*)d_in[8];
    const float* agw  = (const float*)d_in[9];
    const float* qm   = (const float*)d_in[10];
    const float* km   = (const float*)d_in[11];
    const float* vm   = (const float*)d_in[12];
    const int*   wsp  = (n_in > 13) ? (const int*)d_in[13] : nullptr;
    float* out = (float*)d_out;

    float *pqw, *pkw, *pvw, *pq, *pk, *pv, *py;
    cudaGetSymbolAddress((void**)&pqw, g_qw);
    cudaGetSymbolAddress((void**)&pkw, g_kw);
    cudaGetSymbolAddress((void**)&pvw, g_vw);
    cudaGetSymbolAddress((void**)&pq,  g_q);
    cudaGetSymbolAddress((void**)&pk,  g_k);
    cudaGetSymbolAddress((void**)&pv,  g_v);
    cudaGetSymbolAddress((void**)&py,  g_y);

    // 1) fuse mixes into weights
    fuse_kernel<<<dim3(CC, 3), 256>>>(cqw, ckw, cvw, qm, km, vm);

    // 2) QKV projections
    gemm_nt_kernel<<<dim3(NROWS/128, CC/128), 256>>>(x, pqw, pq, NROWS, CC, CC);
    gemm_nt_kernel<<<dim3(NROWS/128, CC/128), 256>>>(x, pkw, pk, NROWS, CC, CC);
    gemm_nt_kernel<<<dim3(NROWS/128, CC/128), 256>>>(x, pvw, pv, NROWS, CC, CC);

    // 3) gates + rope + rmsnorm
    post_kernel<<<(NROWS*HH*32)/256, 256>>>(x, ve, cosb, sinb, vgw, agw);

    // 4) flash attention
    cudaFuncSetAttribute(attn_kernel, cudaFuncAttributeMaxDynamicSharedMemorySize, ATTN_SMEM);
    attn_kernel<<<dim3(TT/64, HH, BB), 128, ATTN_SMEM>>>(wsp);

    // 5) output projection
    gemm_nt_kernel<<<dim3(NROWS/128, CC/128), 256>>>(py, cpw, out, NROWS, CC, CC);
}

// round 3
// speedup vs baseline: 1.0424x; 1.0424x over previous
#include <cuda_runtime.h>
#include <cstdint>
#include <cstddef>
#include <math.h>

#define BB 2
#define TT 2048
#define CC 1024
#define HH 16
#define NROWS (BB*TT)   // 4096

// ---------------- scratch (static device allocations; no cudaMalloc) -------
__device__ float g_qw[CC*CC];
__device__ float g_kw[CC*CC];
__device__ float g_vw[CC*CC];
__device__ float g_q[NROWS*CC];
__device__ float g_k[NROWS*CC];
__device__ float g_v[NROWS*CC];
__device__ float g_y[NROWS*CC];
__device__ float g_ga[NROWS*HH];

__device__ __forceinline__ void cp_async16(uint32_t saddr, const void* g) {
    asm volatile("cp.async.cg.shared.global [%0], [%1], 16;\n" :: "r"(saddr), "l"(g));
}
__device__ __forceinline__ void cp_commit() {
    asm volatile("cp.async.commit_group;\n");
}
__device__ __forceinline__ void cp_wait0() {
    asm volatile("cp.async.wait_group 0;\n");
}

// ---------------- 1) fuse mix into weights ---------------------------------
__global__ void fuse_kernel(const float* __restrict__ cq, const float* __restrict__ ck,
                            const float* __restrict__ cv, const float* __restrict__ qm,
                            const float* __restrict__ km, const float* __restrict__ vm) {
    int row = blockIdx.x;
    int wi  = blockIdx.y;
    const float* W = (wi == 0) ? cq : (wi == 1) ? ck : cv;
    const float* M = (wi == 0) ? qm : (wi == 1) ? km : vm;
    float* O       = (wi == 0) ? g_qw : (wi == 1) ? g_kw : g_vw;
    int h = row >> 6, d = row & 63;
    float mx[16];
#pragma unroll
    for (int m = 0; m < 16; m++) mx[m] = M[h*16 + m];
    for (int c = threadIdx.x; c < CC; c += blockDim.x) {
        float s = 0.f;
#pragma unroll
        for (int m = 0; m < 16; m++) s += mx[m] * W[(m*64 + d)*CC + c];
        O[row*CC + c] = s;
    }
}

// ---------------- 2) NT SGEMM, double-buffered, up to 3 problems via z ------
__global__ __launch_bounds__(256, 2) void gemm_nt_kernel(
    const float* __restrict__ A,
    const float* __restrict__ B0, float* __restrict__ C0,
    const float* __restrict__ B1, float* __restrict__ C1,
    const float* __restrict__ B2, float* __restrict__ C2,
    int K) {
    const float* Bm = (blockIdx.z == 0) ? B0 : (blockIdx.z == 1) ? B1 : B2;
    float*       Cm = (blockIdx.z == 0) ? C0 : (blockIdx.z == 1) ? C1 : C2;
    const int N = CC;

    __shared__ float As[2][8][132];
    __shared__ float Bs[2][8][132];
    const int tid = threadIdx.x;
    const int tx = tid & 15, ty = tid >> 4;
    const int brow = blockIdx.x * 128, bcol = blockIdx.y * 128;

    const int lr = tid >> 1;
    const int lc = (tid & 1) * 4;
    const float* Abase = A  + (size_t)(brow + lr) * K + lc;
    const float* Bbase = Bm + (size_t)(bcol + lr) * K + lc;

    float acc[8][8];
#pragma unroll
    for (int i = 0; i < 8; i++)
#pragma unroll
        for (int j = 0; j < 8; j++) acc[i][j] = 0.f;

    // prologue: stage 0
    {
        float4 a = *(const float4*)Abase;
        float4 b = *(const float4*)Bbase;
        As[0][lc+0][lr] = a.x; As[0][lc+1][lr] = a.y;
        As[0][lc+2][lr] = a.z; As[0][lc+3][lr] = a.w;
        Bs[0][lc+0][lr] = b.x; Bs[0][lc+1][lr] = b.y;
        Bs[0][lc+2][lr] = b.z; Bs[0][lc+3][lr] = b.w;
    }
    __syncthreads();

    int p = 0;
    for (int kk = 0; kk < K; kk += 8) {
        const bool has = (kk + 8) < K;
        float4 an, bn;
        if (has) {
            an = *(const float4*)(Abase + kk + 8);
            bn = *(const float4*)(Bbase + kk + 8);
        }
#pragma unroll
        for (int k = 0; k < 8; k++) {
            float4 a0 = *(const float4*)&As[p][k][ty*8];
            float4 a1 = *(const float4*)&As[p][k][ty*8 + 4];
            float4 b0 = *(const float4*)&Bs[p][k][tx*8];
            float4 b1 = *(const float4*)&Bs[p][k][tx*8 + 4];
            float ar[8] = {a0.x,a0.y,a0.z,a0.w,a1.x,a1.y,a1.z,a1.w};
            float br[8] = {b0.x,b0.y,b0.z,b0.w,b1.x,b1.y,b1.z,b1.w};
#pragma unroll
            for (int i = 0; i < 8; i++)
#pragma unroll
                for (int j = 0; j < 8; j++) acc[i][j] += ar[i]*br[j];
        }
        if (has) {
            int q = p ^ 1;
            As[q][lc+0][lr] = an.x; As[q][lc+1][lr] = an.y;
            As[q][lc+2][lr] = an.z; As[q][lc+3][lr] = an.w;
            Bs[q][lc+0][lr] = bn.x; Bs[q][lc+1][lr] = bn.y;
            Bs[q][lc+2][lr] = bn.z; Bs[q][lc+3][lr] = bn.w;
            __syncthreads();
            p = q;
        }
    }
#pragma unroll
    for (int i = 0; i < 8; i++) {
        int row = brow + ty*8 + i;
        float* dst = Cm + (size_t)row * N + bcol + tx*8;
        float4 w0 = {acc[i][0], acc[i][1], acc[i][2], acc[i][3]};
        float4 w1 = {acc[i][4], acc[i][5], acc[i][6], acc[i][7]};
        *(float4*)dst = w0;
        *(float4*)(dst + 4) = w1;
    }
}

// ---------------- 3) gates + RoPE + RMSNorm (one warp per (b,t,h)) ----------
__global__ void post_kernel(const float* __restrict__ x, const float* __restrict__ ve,
                            const float* __restrict__ cosb, const float* __restrict__ sinb,
                            const float* __restrict__ vgw, const float* __restrict__ agw) {
    int gw   = (blockIdx.x * blockDim.x + threadIdx.x) >> 5;
    int lane = threadIdx.x & 31;
    if (gw >= NROWS*HH) return;
    int h  = gw % HH;
    int bt = gw / HH;
    int t  = bt % TT;
    size_t xbase = (size_t)bt * CC;

    float gv = x[xbase + lane] * vgw[h*32 + lane];
#pragma unroll
    for (int o = 16; o > 0; o >>= 1) gv += __shfl_xor_sync(0xffffffffu, gv, o);
    float gate_v = 2.f / (1.f + __expf(-gv));

    float ga = (lane < 12) ? x[xbase + lane] * agw[h*12 + lane] : 0.f;
#pragma unroll
    for (int o = 16; o > 0; o >>= 1) ga += __shfl_xor_sync(0xffffffffu, ga, o);
    if (lane == 0) g_ga[(size_t)bt*HH + h] = 1.f / (1.f + __expf(-ga));

    size_t idx = xbase + h*64;
    g_v[idx + lane]      += gate_v * ve[idx + lane];
    g_v[idx + lane + 32] += gate_v * ve[idx + lane + 32];

    float cs = cosb[t*32 + lane], sn = sinb[t*32 + lane];
    {
        float q1 = g_q[idx + lane], q2 = g_q[idx + lane + 32];
        float r1 =  q1*cs + q2*sn;
        float r2 = -q1*sn + q2*cs;
        float ss = r1*r1 + r2*r2;
#pragma unroll
        for (int o = 16; o > 0; o >>= 1) ss += __shfl_xor_sync(0xffffffffu, ss, o);
        float sc = rsqrtf(ss * (1.f/64.f) + 1e-6f);
        g_q[idx + lane] = r1*sc; g_q[idx + lane + 32] = r2*sc;
    }
    {
        float k1 = g_k[idx + lane], k2 = g_k[idx + lane + 32];
        float r1 =  k1*cs + k2*sn;
        float r2 = -k1*sn + k2*cs;
        float ss = r1*r1 + r2*r2;
#pragma unroll
        for (int o = 16; o > 0; o >>= 1) ss += __shfl_xor_sync(0xffffffffu, ss, o);
        float sc = rsqrtf(ss * (1.f/64.f) + 1e-6f);
        g_k[idx + lane] = r1*sc; g_k[idx + lane + 32] = r2*sc;
    }
}

// ---------------- 4) flash attention, fp32, BM=BN=64, pipelined ------------
#define SMP 68
#define ATTN_SMEM (5*64*SMP*4)   // Qs, Ks, Ps, Vs x2

__global__ __launch_bounds__(128) void attn_kernel(const int* __restrict__ wsp) {
    extern __shared__ float smf[];
    float* Qs  = smf;              // [d][m]
    float* Ks  = Qs  + 64*SMP;     // [d][n]
    float* Ps  = Ks  + 64*SMP;     // [n][m]
    float* Vs0 = Ps  + 64*SMP;     // [n][d]
    float* Vs1 = Vs0 + 64*SMP;

    const int qt = blockIdx.x, h = blockIdx.y, b = blockIdx.z;
    const int tid = threadIdx.x;
    const int tr = tid >> 3;       // 0..15 -> 4 q rows
    const int tc = tid & 7;        // 0..7  -> 8 cols
    const int q0 = qt * 64;

    int wsv = wsp ? *wsp : -1;
    const bool use_w = (wsv >= 0) && (wsv < TT - 1);
    int jt0 = 0;
    if (use_w) {
        int lo = q0 - wsv - 63;    // need kv0+63 >= q0-wsv
        if (lo > 0) jt0 = (lo + 63) >> 6;
    }

    const int m    = tid >> 1;
    const int half = tid & 1;
    const int hoff = h*64 + half*32;

    // load Q tile (transposed into [d][m])
    {
        const float* src = g_q + ((size_t)(b*TT + q0 + m))*CC + hoff;
#pragma unroll
        for (int i = 0; i < 8; i++) {
            float4 v = *(const float4*)(src + i*4);
            int d = half*32 + i*4;
            Qs[(d+0)*SMP + m] = v.x; Qs[(d+1)*SMP + m] = v.y;
            Qs[(d+2)*SMP + m] = v.z; Qs[(d+3)*SMP + m] = v.w;
        }
    }

    // prologue: K tile jt0 -> regs, V tile jt0 -> cp.async into Vs0
    float4 kreg[8];
    {
        int pos = jt0*64 + m;
        int srcpos = (half == 0) ? pos : (pos > 0 ? pos - 1 : 0);
        const float* ks = g_k + ((size_t)(b*TT + srcpos))*CC + hoff;
#pragma unroll
        for (int i = 0; i < 8; i++) kreg[i] = *(const float4*)(ks + i*4);
        const float* vsrc = g_v + ((size_t)(b*TT + pos))*CC + hoff;
        uint32_t vdst = (uint32_t)__cvta_generic_to_shared(Vs0 + m*SMP + half*32);
#pragma unroll
        for (int i = 0; i < 8; i++) cp_async16(vdst + i*16, vsrc + i*4);
        cp_commit();
    }

    float o[4][8];
    float mi[4], li[4];
#pragma unroll
    for (int r = 0; r < 4; r++) {
        mi[r] = -1e30f; li[r] = 0.f;
#pragma unroll
        for (int c = 0; c < 8; c++) o[r][c] = 0.f;
    }

    float* Vcur = Vs0;
    float* Vnxt = Vs1;

    for (int jt = jt0; jt <= qt; jt++) {
        const int kv0 = jt * 64;
        cp_wait0();
        // store staged K (transposed)
#pragma unroll
        for (int i = 0; i < 8; i++) {
            int d = half*32 + i*4;
            Ks[(d+0)*SMP + m] = kreg[i].x; Ks[(d+1)*SMP + m] = kreg[i].y;
            Ks[(d+2)*SMP + m] = kreg[i].z; Ks[(d+3)*SMP + m] = kreg[i].w;
        }
        __syncthreads();

        // S = Q K^T
        float s[4][8];
#pragma unroll
        for (int r = 0; r < 4; r++)
#pragma unroll
            for (int c = 0; c < 8; c++) s[r][c] = 0.f;
#pragma unroll 16
        for (int d = 0; d < 64; d++) {
            float4 a  = *(const float4*)(Qs + d*SMP + tr*4);
            float4 b0 = *(const float4*)(Ks + d*SMP + tc*8);
            float4 b1 = *(const float4*)(Ks + d*SMP + tc*8 + 4);
            float ar[4] = {a.x, a.y, a.z, a.w};
            float br[8] = {b0.x,b0.y,b0.z,b0.w,b1.x,b1.y,b1.z,b1.w};
#pragma unroll
            for (int r = 0; r < 4; r++)
#pragma unroll
                for (int c = 0; c < 8; c++) s[r][c] += ar[r]*br[c];
        }
        // mask + scale
#pragma unroll
        for (int r = 0; r < 4; r++) {
            int qi = q0 + tr*4 + r;
#pragma unroll
            for (int c = 0; c < 8; c++) {
                int kj = kv0 + tc*8 + c;
                bool ok = (kj <= qi) && (!use_w || (qi - kj) <= wsv);
                s[r][c] = ok ? s[r][c]*0.125f : -1e30f;
            }
        }
        // online softmax (row stats over the 8 threads of a row group)
#pragma unroll
        for (int r = 0; r < 4; r++) {
            float mx = s[r][0];
#pragma unroll
            for (int c = 1; c < 8; c++) mx = fmaxf(mx, s[r][c]);
            mx = fmaxf(mx, __shfl_xor_sync(0xffffffffu, mx, 1));
            mx = fmaxf(mx, __shfl_xor_sync(0xffffffffu, mx, 2));
            mx = fmaxf(mx, __shfl_xor_sync(0xffffffffu, mx, 4));
            float mnew = fmaxf(fmaxf(mi[r], mx), -1e29f);  // clamp: fully-masked tile -> p=0
            float corr = __expf(mi[r] - mnew);
            float sum = 0.f;
#pragma unroll
            for (int c = 0; c < 8; c++) {
                float p = __expf(s[r][c] - mnew);
                s[r][c] = p; sum += p;
            }
            sum += __shfl_xor_sync(0xffffffffu, sum, 1);
            sum += __shfl_xor_sync(0xffffffffu, sum, 2);
            sum += __shfl_xor_sync(0xffffffffu, sum, 4);
            li[r] = li[r]*corr + sum;
            mi[r] = mnew;
#pragma unroll
            for (int c = 0; c < 8; c++) o[r][c] *= corr;
#pragma unroll
            for (int c = 0; c < 8; c++)
                Ps[(tc*8 + c)*SMP + tr*4 + r] = s[r][c];
        }

        // prefetch next tile (hidden behind PV)
        if (jt < qt) {
            int pos = kv0 + 64 + m;
            int srcpos = (half == 0) ? pos : (pos - 1);
            const float* ks = g_k + ((size_t)(b*TT + srcpos))*CC + hoff;
#pragma unroll
            for (int i = 0; i < 8; i++) kreg[i] = *(const float4*)(ks + i*4);
            const float* vsrc = g_v + ((size_t)(b*TT + pos))*CC + hoff;
            uint32_t vdst = (uint32_t)__cvta_generic_to_shared(Vnxt + m*SMP + half*32);
#pragma unroll
            for (int i = 0; i < 8; i++) cp_async16(vdst + i*16, vsrc + i*4);
            cp_commit();
        }
        __syncthreads();

        // O += P V
#pragma unroll 16
        for (int n = 0; n < 64; n++) {
            float4 p  = *(const float4*)(Ps + n*SMP + tr*4);
            float4 v0 = *(const float4*)(Vcur + n*SMP + tc*8);
            float4 v1 = *(const float4*)(Vcur + n*SMP + tc*8 + 4);
            float pr[4] = {p.x, p.y, p.z, p.w};
            float vr[8] = {v0.x,v0.y,v0.z,v0.w,v1.x,v1.y,v1.z,v1.w};
#pragma unroll
            for (int r = 0; r < 4; r++)
#pragma unroll
                for (int c = 0; c < 8; c++) o[r][c] += pr[r]*vr[c];
        }
        { float* t = Vcur; Vcur = Vnxt; Vnxt = t; }
    }

    // epilogue: normalize, apply attn gate, write y
#pragma unroll
    for (int r = 0; r < 4; r++) {
        int qi = q0 + tr*4 + r;
        float g = g_ga[(size_t)(b*TT + qi)*HH + h];
        float inv = g / li[r];
        float* dst = g_y + ((size_t)(b*TT + qi))*CC + h*64 + tc*8;
        float4 w0 = {o[r][0]*inv, o[r][1]*inv, o[r][2]*inv, o[r][3]*inv};
        float4 w1 = {o[r][4]*inv, o[r][5]*inv, o[r][6]*inv, o[r][7]*inv};
        *(float4*)dst = w0;
        *(float4*)(dst + 4) = w1;
    }
}

// ---------------- launch ----------------------------------------------------
extern "C" void kernel_launch(void* const* d_in, const int* in_sizes, int n_in,
                              void* d_out, int out_size) {
    const float* x    = (const float*)d_in[0];
    const float* ve   = (const float*)d_in[1];
    const float* cosb = (const float*)d_in[2];
    const float* sinb = (const float*)d_in[3];
    const float* cqw  = (const float*)d_in[4];
    const float* ckw  = (const float*)d_in[5];
    const float* cvw  = (const float*)d_in[6];
    const float* cpw  = (const float*)d_in[7];
    const float* vgw  = (const float*)d_in[8];
    const float* agw  = (const float*)d_in[9];
    const float* qm   = (const float*)d_in[10];
    const float* km   = (const float*)d_in[11];
    const float* vm   = (const float*)d_in[12];
    const int*   wsp  = (n_in > 13) ? (const int*)d_in[13] : nullptr;
    float* out = (float*)d_out;

    float *pqw, *pkw, *pvw, *pq, *pk, *pv, *py;
    cudaGetSymbolAddress((void**)&pqw, g_qw);
    cudaGetSymbolAddress((void**)&pkw, g_kw);
    cudaGetSymbolAddress((void**)&pvw, g_vw);
    cudaGetSymbolAddress((void**)&pq,  g_q);
    cudaGetSymbolAddress((void**)&pk,  g_k);
    cudaGetSymbolAddress((void**)&pv,  g_v);
    cudaGetSymbolAddress((void**)&py,  g_y);

    // 1) fuse mixes into weights
    fuse_kernel<<<dim3(CC, 3), 256>>>(cqw, ckw, cvw, qm, km, vm);

    // 2) QKV projections (one launch, z selects problem)
    gemm_nt_kernel<<<dim3(NROWS/128, CC/128, 3), 256>>>(x, pqw, pq, pkw, pk, pvw, pv, CC);

    // 3) gates + rope + rmsnorm
    post_kernel<<<(NROWS*HH*32)/256, 256>>>(x, ve, cosb, sinb, vgw, agw);

    // 4) flash attention
    cudaFuncSetAttribute(attn_kernel, cudaFuncAttributeMaxDynamicSharedMemorySize, ATTN_SMEM);
    attn_kernel<<<dim3(TT/64, HH, BB), 128, ATTN_SMEM>>>(wsp);

    // 5) output projection
    gemm_nt_kernel<<<dim3(NROWS/128, CC/128, 1), 256>>>(py, cpw, out, cpw, out, cpw, out, CC);
}

// round 4
// speedup vs baseline: 1.0480x; 1.0053x over previous
#include <cuda_runtime.h>
#include <cstdint>
#include <cstddef>
#include <math.h>

#define BB 2
#define TT 2048
#define CC 1024
#define HH 16
#define NROWS (BB*TT)   // 4096

// ---------------- scratch (static device allocations; no cudaMalloc) -------
__device__ float g_qw[CC*CC];
__device__ float g_kw[CC*CC];
__device__ float g_vw[CC*CC];
__device__ float g_q[NROWS*CC];
__device__ float g_k[NROWS*CC];
__device__ float g_v[NROWS*CC];
__device__ float g_y[NROWS*CC];
__device__ float g_ga[NROWS*HH];

__device__ __forceinline__ void cp_async16(uint32_t saddr, const void* g) {
    asm volatile("cp.async.cg.shared.global [%0], [%1], 16;\n" :: "r"(saddr), "l"(g));
}
__device__ __forceinline__ void cp_commit() {
    asm volatile("cp.async.commit_group;\n");
}
__device__ __forceinline__ void cp_wait0() {
    asm volatile("cp.async.wait_group 0;\n");
}

// ---------------- 1) fuse mix into weights ---------------------------------
__global__ void fuse_kernel(const float* __restrict__ cq, const float* __restrict__ ck,
                            const float* __restrict__ cv, const float* __restrict__ qm,
                            const float* __restrict__ km, const float* __restrict__ vm) {
    int row = blockIdx.x;
    int wi  = blockIdx.y;
    const float* W = (wi == 0) ? cq : (wi == 1) ? ck : cv;
    const float* M = (wi == 0) ? qm : (wi == 1) ? km : vm;
    float* O       = (wi == 0) ? g_qw : (wi == 1) ? g_kw : g_vw;
    int h = row >> 6, d = row & 63;
    float mx[16];
#pragma unroll
    for (int m = 0; m < 16; m++) mx[m] = M[h*16 + m];
    for (int c = threadIdx.x; c < CC; c += blockDim.x) {
        float s = 0.f;
#pragma unroll
        for (int m = 0; m < 16; m++) s += mx[m] * W[(m*64 + d)*CC + c];
        O[row*CC + c] = s;
    }
}

// ---------------- 2) NT SGEMM, double-buffered, up to 3 problems via z ------
__global__ __launch_bounds__(256, 2) void gemm_nt_kernel(
    const float* __restrict__ A,
    const float* __restrict__ B0, float* __restrict__ C0,
    const float* __restrict__ B1, float* __restrict__ C1,
    const float* __restrict__ B2, float* __restrict__ C2,
    int K) {
    const float* Bm = (blockIdx.z == 0) ? B0 : (blockIdx.z == 1) ? B1 : B2;
    float*       Cm = (blockIdx.z == 0) ? C0 : (blockIdx.z == 1) ? C1 : C2;
    const int N = CC;

    __shared__ float As[2][8][132];
    __shared__ float Bs[2][8][132];
    const int tid = threadIdx.x;
    const int tx = tid & 15, ty = tid >> 4;
    const int brow = blockIdx.x * 128, bcol = blockIdx.y * 128;

    const int lr = tid >> 1;
    const int lc = (tid & 1) * 4;
    const float* Abase = A  + (size_t)(brow + lr) * K + lc;
    const float* Bbase = Bm + (size_t)(bcol + lr) * K + lc;

    float acc[8][8];
#pragma unroll
    for (int i = 0; i < 8; i++)
#pragma unroll
        for (int j = 0; j < 8; j++) acc[i][j] = 0.f;

    {
        float4 a = *(const float4*)Abase;
        float4 b = *(const float4*)Bbase;
        As[0][lc+0][lr] = a.x; As[0][lc+1][lr] = a.y;
        As[0][lc+2][lr] = a.z; As[0][lc+3][lr] = a.w;
        Bs[0][lc+0][lr] = b.x; Bs[0][lc+1][lr] = b.y;
        Bs[0][lc+2][lr] = b.z; Bs[0][lc+3][lr] = b.w;
    }
    __syncthreads();

    int p = 0;
    for (int kk = 0; kk < K; kk += 8) {
        const bool has = (kk + 8) < K;
        float4 an, bn;
        if (has) {
            an = *(const float4*)(Abase + kk + 8);
            bn = *(const float4*)(Bbase + kk + 8);
        }
#pragma unroll
        for (int k = 0; k < 8; k++) {
            float4 a0 = *(const float4*)&As[p][k][ty*8];
            float4 a1 = *(const float4*)&As[p][k][ty*8 + 4];
            float4 b0 = *(const float4*)&Bs[p][k][tx*8];
            float4 b1 = *(const float4*)&Bs[p][k][tx*8 + 4];
            float ar[8] = {a0.x,a0.y,a0.z,a0.w,a1.x,a1.y,a1.z,a1.w};
            float br[8] = {b0.x,b0.y,b0.z,b0.w,b1.x,b1.y,b1.z,b1.w};
#pragma unroll
            for (int i = 0; i < 8; i++)
#pragma unroll
                for (int j = 0; j < 8; j++) acc[i][j] += ar[i]*br[j];
        }
        if (has) {
            int q = p ^ 1;
            As[q][lc+0][lr] = an.x; As[q][lc+1][lr] = an.y;
            As[q][lc+2][lr] = an.z; As[q][lc+3][lr] = an.w;
            Bs[q][lc+0][lr] = bn.x; Bs[q][lc+1][lr] = bn.y;
            Bs[q][lc+2][lr] = bn.z; Bs[q][lc+3][lr] = bn.w;
            __syncthreads();
            p = q;
        }
    }
#pragma unroll
    for (int i = 0; i < 8; i++) {
        int row = brow + ty*8 + i;
        float* dst = Cm + (size_t)row * N + bcol + tx*8;
        float4 w0 = {acc[i][0], acc[i][1], acc[i][2], acc[i][3]};
        float4 w1 = {acc[i][4], acc[i][5], acc[i][6], acc[i][7]};
        *(float4*)dst = w0;
        *(float4*)(dst + 4) = w1;
    }
}

// ---------------- 3) gates + RoPE + RMSNorm (one warp per (b,t,h)) ----------
__global__ void post_kernel(const float* __restrict__ x, const float* __restrict__ ve,
                            const float* __restrict__ cosb, const float* __restrict__ sinb,
                            const float* __restrict__ vgw, const float* __restrict__ agw) {
    int gw   = (blockIdx.x * blockDim.x + threadIdx.x) >> 5;
    int lane = threadIdx.x & 31;
    if (gw >= NROWS*HH) return;
    int h  = gw % HH;
    int bt = gw / HH;
    int t  = bt % TT;
    size_t xbase = (size_t)bt * CC;

    float gv = x[xbase + lane] * vgw[h*32 + lane];
#pragma unroll
    for (int o = 16; o > 0; o >>= 1) gv += __shfl_xor_sync(0xffffffffu, gv, o);
    float gate_v = 2.f / (1.f + __expf(-gv));

    float ga = (lane < 12) ? x[xbase + lane] * agw[h*12 + lane] : 0.f;
#pragma unroll
    for (int o = 16; o > 0; o >>= 1) ga += __shfl_xor_sync(0xffffffffu, ga, o);
    if (lane == 0) g_ga[(size_t)bt*HH + h] = 1.f / (1.f + __expf(-ga));

    size_t idx = xbase + h*64;
    g_v[idx + lane]      += gate_v * ve[idx + lane];
    g_v[idx + lane + 32] += gate_v * ve[idx + lane + 32];

    float cs = cosb[t*32 + lane], sn = sinb[t*32 + lane];
    {
        float q1 = g_q[idx + lane], q2 = g_q[idx + lane + 32];
        float r1 =  q1*cs + q2*sn;
        float r2 = -q1*sn + q2*cs;
        float ss = r1*r1 + r2*r2;
#pragma unroll
        for (int o = 16; o > 0; o >>= 1) ss += __shfl_xor_sync(0xffffffffu, ss, o);
        float sc = rsqrtf(ss * (1.f/64.f) + 1e-6f);
        g_q[idx + lane] = r1*sc; g_q[idx + lane + 32] = r2*sc;
    }
    {
        float k1 = g_k[idx + lane], k2 = g_k[idx + lane + 32];
        float r1 =  k1*cs + k2*sn;
        float r2 = -k1*sn + k2*cs;
        float ss = r1*r1 + r2*r2;
#pragma unroll
        for (int o = 16; o > 0; o >>= 1) ss += __shfl_xor_sync(0xffffffffu, ss, o);
        float sc = rsqrtf(ss * (1.f/64.f) + 1e-6f);
        g_k[idx + lane] = r1*sc; g_k[idx + lane + 32] = r2*sc;
    }
}

// ---------------- 4) flash attention, fp32, BM=BN=64, 52KB smem, 4 CTA/SM --
#define SMP 68
#define ATTN_SMEM (3*64*SMP*4)   // Qs, KPs (K aliased with P), Vs

__global__ __launch_bounds__(128, 4) void attn_kernel(const int* __restrict__ wsp) {
    extern __shared__ float smf[];
    float* Qs  = smf;              // [d][m]
    float* KPs = Qs  + 64*SMP;     // K as [d][n] during S; P as [n][m] during PV
    float* Vs  = KPs + 64*SMP;     // [n][d]

    const int qt = (TT/64 - 1) - blockIdx.x;   // heavy blocks launch first
    const int h = blockIdx.y, b = blockIdx.z;
    const int tid = threadIdx.x;
    const int tr = tid >> 3;       // 0..15 -> 4 q rows
    const int tc = tid & 7;        // 0..7  -> 8 cols
    const int q0 = qt * 64;

    int wsv = wsp ? *wsp : -1;
    const bool use_w = (wsv >= 0) && (wsv < TT - 1);
    int jt0 = 0;
    if (use_w) {
        int lo = q0 - wsv - 63;
        if (lo > 0) jt0 = (lo + 63) >> 6;
    }

    const int m    = tid >> 1;
    const int half = tid & 1;
    const int hoff = h*64 + half*32;

    // load Q tile (transposed into [d][m])
    {
        const float* src = g_q + ((size_t)(b*TT + q0 + m))*CC + hoff;
#pragma unroll
        for (int i = 0; i < 8; i++) {
            float4 v = *(const float4*)(src + i*4);
            int d = half*32 + i*4;
            Qs[(d+0)*SMP + m] = v.x; Qs[(d+1)*SMP + m] = v.y;
            Qs[(d+2)*SMP + m] = v.z; Qs[(d+3)*SMP + m] = v.w;
        }
    }

    // prologue: K tile jt0 -> regs
    float4 kreg[8];
    {
        int pos = jt0*64 + m;
        int srcpos = (half == 0) ? pos : (pos > 0 ? pos - 1 : 0);
        const float* ks = g_k + ((size_t)(b*TT + srcpos))*CC + hoff;
#pragma unroll
        for (int i = 0; i < 8; i++) kreg[i] = *(const float4*)(ks + i*4);
    }

    float o[4][8];
    float mi[4], li[4];
#pragma unroll
    for (int r = 0; r < 4; r++) {
        mi[r] = -1e30f; li[r] = 0.f;
#pragma unroll
        for (int c = 0; c < 8; c++) o[r][c] = 0.f;
    }

    const uint32_t vdst = (uint32_t)__cvta_generic_to_shared(Vs + m*SMP + half*32);

    for (int jt = jt0; jt <= qt; jt++) {
        const int kv0 = jt * 64;
        // store staged K (transposed) into KPs
#pragma unroll
        for (int i = 0; i < 8; i++) {
            int d = half*32 + i*4;
            KPs[(d+0)*SMP + m] = kreg[i].x; KPs[(d+1)*SMP + m] = kreg[i].y;
            KPs[(d+2)*SMP + m] = kreg[i].z; KPs[(d+3)*SMP + m] = kreg[i].w;
        }
        __syncthreads();   // (1) K visible; previous PV done with Vs

        // launch V[jt] load (covered by S + softmax below)
        {
            const float* vsrc = g_v + ((size_t)(b*TT + kv0 + m))*CC + hoff;
#pragma unroll
            for (int i = 0; i < 8; i++) cp_async16(vdst + i*16, vsrc + i*4);
            cp_commit();
        }

        // S = Q K^T
        float s[4][8];
#pragma unroll
        for (int r = 0; r < 4; r++)
#pragma unroll
            for (int c = 0; c < 8; c++) s[r][c] = 0.f;
#pragma unroll 16
        for (int d = 0; d < 64; d++) {
            float4 a  = *(const float4*)(Qs + d*SMP + tr*4);
            float4 b0 = *(const float4*)(KPs + d*SMP + tc*8);
            float4 b1 = *(const float4*)(KPs + d*SMP + tc*8 + 4);
            float ar[4] = {a.x, a.y, a.z, a.w};
            float br[8] = {b0.x,b0.y,b0.z,b0.w,b1.x,b1.y,b1.z,b1.w};
#pragma unroll
            for (int r = 0; r < 4; r++)
#pragma unroll
                for (int c = 0; c < 8; c++) s[r][c] += ar[r]*br[c];
        }

        // prefetch next K tile into regs (hidden behind softmax + PV)
        if (jt < qt) {
            int pos = kv0 + 64 + m;
            int srcpos = (half == 0) ? pos : (pos - 1);
            const float* ks = g_k + ((size_t)(b*TT + srcpos))*CC + hoff;
#pragma unroll
            for (int i = 0; i < 8; i++) kreg[i] = *(const float4*)(ks + i*4);
        }

        // mask + scale
#pragma unroll
        for (int r = 0; r < 4; r++) {
            int qi = q0 + tr*4 + r;
#pragma unroll
            for (int c = 0; c < 8; c++) {
                int kj = kv0 + tc*8 + c;
                bool ok = (kj <= qi) && (!use_w || (qi - kj) <= wsv);
                s[r][c] = ok ? s[r][c]*0.125f : -1e30f;
            }
        }
        // online softmax
#pragma unroll
        for (int r = 0; r < 4; r++) {
            float mx = s[r][0];
#pragma unroll
            for (int c = 1; c < 8; c++) mx = fmaxf(mx, s[r][c]);
            mx = fmaxf(mx, __shfl_xor_sync(0xffffffffu, mx, 1));
            mx = fmaxf(mx, __shfl_xor_sync(0xffffffffu, mx, 2));
            mx = fmaxf(mx, __shfl_xor_sync(0xffffffffu, mx, 4));
            float mnew = fmaxf(fmaxf(mi[r], mx), -1e29f);
            float corr = __expf(mi[r] - mnew);
            float sum = 0.f;
#pragma unroll
            for (int c = 0; c < 8; c++) {
                float p = __expf(s[r][c] - mnew);
                s[r][c] = p; sum += p;
            }
            sum += __shfl_xor_sync(0xffffffffu, sum, 1);
            sum += __shfl_xor_sync(0xffffffffu, sum, 2);
            sum += __shfl_xor_sync(0xffffffffu, sum, 4);
            li[r] = li[r]*corr + sum;
            mi[r] = mnew;
#pragma unroll
            for (int c = 0; c < 8; c++) o[r][c] *= corr;
        }
        __syncthreads();   // (2) all S-reads of KPs done -> safe to overwrite with P

        // write P transposed [n][m] into KPs
#pragma unroll
        for (int r = 0; r < 4; r++)
#pragma unroll
            for (int c = 0; c < 8; c++)
                KPs[(tc*8 + c)*SMP + tr*4 + r] = s[r][c];

        cp_wait0();
        __syncthreads();   // (3) P + V visible

        // O += P V
#pragma unroll 16
        for (int n = 0; n < 64; n++) {
            float4 p  = *(const float4*)(KPs + n*SMP + tr*4);
            float4 v0 = *(const float4*)(Vs + n*SMP + tc*8);
            float4 v1 = *(const float4*)(Vs + n*SMP + tc*8 + 4);
            float pr[4] = {p.x, p.y, p.z, p.w};
            float vr[8] = {v0.x,v0.y,v0.z,v0.w,v1.x,v1.y,v1.z,v1.w};
#pragma unroll
            for (int r = 0; r < 4; r++)
#pragma unroll
                for (int c = 0; c < 8; c++) o[r][c] += pr[r]*vr[c];
        }
    }

    // epilogue: normalize, apply attn gate, write y
#pragma unroll
    for (int r = 0; r < 4; r++) {
        int qi = q0 + tr*4 + r;
        float g = g_ga[(size_t)(b*TT + qi)*HH + h];
        float inv = g / li[r];
        float* dst = g_y + ((size_t)(b*TT + qi))*CC + h*64 + tc*8;
        float4 w0 = {o[r][0]*inv, o[r][1]*inv, o[r][2]*inv, o[r][3]*inv};
        float4 w1 = {o[r][4]*inv, o[r][5]*inv, o[r][6]*inv, o[r][7]*inv};
        *(float4*)dst = w0;
        *(float4*)(dst + 4) = w1;
    }
}

// ---------------- launch ----------------------------------------------------
extern "C" void kernel_launch(void* const* d_in, const int* in_sizes, int n_in,
                              void* d_out, int out_size) {
    const float* x    = (const float*)d_in[0];
    const float* ve   = (const float*)d_in[1];
    const float* cosb = (const float*)d_in[2];
    const float* sinb = (const float*)d_in[3];
    const float* cqw  = (const float*)d_in[4];
    const float* ckw  = (const float*)d_in[5];
    const float* cvw  = (const float*)d_in[6];
    const float* cpw  = (const float*)d_in[7];
    const float* vgw  = (const float*)d_in[8];
    const float* agw  = (const float*)d_in[9];
    const float* qm   = (const float*)d_in[10];
    const float* km   = (const float*)d_in[11];
    const float* vm   = (const float*)d_in[12];
    const int*   wsp  = (n_in > 13) ? (const int*)d_in[13] : nullptr;
    float* out = (float*)d_out;

    float *pqw, *pkw, *pvw, *pq, *pk, *pv, *py;
    cudaGetSymbolAddress((void**)&pqw, g_qw);
    cudaGetSymbolAddress((void**)&pkw, g_kw);
    cudaGetSymbolAddress((void**)&pvw, g_vw);
    cudaGetSymbolAddress((void**)&pq,  g_q);
    cudaGetSymbolAddress((void**)&pk,  g_k);
    cudaGetSymbolAddress((void**)&pv,  g_v);
    cudaGetSymbolAddress((void**)&py,  g_y);

    // 1) fuse mixes into weights
    fuse_kernel<<<dim3(CC, 3), 256>>>(cqw, ckw, cvw, qm, km, vm);

    // 2) QKV projections (one launch, z selects problem)
    gemm_nt_kernel<<<dim3(NROWS/128, CC/128, 3), 256>>>(x, pqw, pq, pkw, pk, pvw, pv, CC);

    // 3) gates + rope + rmsnorm
    post_kernel<<<(NROWS*HH*32)/256, 256>>>(x, ve, cosb, sinb, vgw, agw);

    // 4) flash attention
    cudaFuncSetAttribute(attn_kernel, cudaFuncAttributeMaxDynamicSharedMemorySize, ATTN_SMEM);
    attn_kernel<<<dim3(TT/64, HH, BB), 128, ATTN_SMEM>>>(wsp);

    // 5) output projection
    gemm_nt_kernel<<<dim3(NROWS/128, CC/128, 1), 256>>>(py, cpw, out, cpw, out, cpw, out, CC);
}